// round 1
// baseline (speedup 1.0000x reference)
#include <cuda_runtime.h>
#include <math.h>

// Problem constants
#define B_  32
#define T_  2048
#define D_  512
#define H_  512
#define G_  2048          // 4*H
#define BT_ 65536         // B*T
#define NCTA_REC 128

// ---------------------------------------------------------------------------
// Scratch (device globals per harness rules: no cudaMalloc anywhere)
// ---------------------------------------------------------------------------
__device__ float g_xg[65536ULL * 2048ULL];   // (T, B, G) layout: xg[t][b][g]
__device__ float g_h[2][B_ * H_];            // double-buffered hidden state
__device__ unsigned g_bar_count;
__device__ unsigned g_bar_phase;             // monotone across graph replays

// ---------------------------------------------------------------------------
// Kernel A: xg[t][b][g] = sum_d x[b][t][d] * W[d][g] + bias[g]
// fp32 SIMT GEMM, 128x128 tile, BK=8, 256 threads, 8x8 per-thread tile.
// ---------------------------------------------------------------------------
__global__ __launch_bounds__(256) void xg_gemm(const float* __restrict__ x,
                                               const float* __restrict__ W,
                                               const float* __restrict__ bias) {
    __shared__ float As[8][128];   // As[k][m]
    __shared__ float Ws[8][128];   // Ws[k][n]

    const int rowBase = blockIdx.y * 128;   // row in (B*T) space
    const int colBase = blockIdx.x * 128;   // col in G space
    const int tid = threadIdx.x;

    const int arow = tid >> 1;              // 0..127
    const int ak4  = (tid & 1) * 4;         // 0 or 4
    const int wrow = tid >> 5;              // 0..7
    const int wc4  = (tid & 31) * 4;        // 0..124
    const int tm   = (tid >> 4) * 8;        // 0..120
    const int tn   = (tid & 15) * 8;        // 0..120

    float acc[8][8];
#pragma unroll
    for (int i = 0; i < 8; i++)
#pragma unroll
        for (int j = 0; j < 8; j++) acc[i][j] = 0.f;

    for (int k0 = 0; k0 < 512; k0 += 8) {
        // Load A tile (transposed into As[k][m])
        float4 av = *(const float4*)&x[(size_t)(rowBase + arow) * 512 + k0 + ak4];
        As[ak4 + 0][arow] = av.x;
        As[ak4 + 1][arow] = av.y;
        As[ak4 + 2][arow] = av.z;
        As[ak4 + 3][arow] = av.w;
        // Load W tile
        *(float4*)&Ws[wrow][wc4] =
            *(const float4*)&W[(size_t)(k0 + wrow) * 2048 + colBase + wc4];
        __syncthreads();

#pragma unroll
        for (int kk = 0; kk < 8; kk++) {
            float a[8], w[8];
            *(float4*)&a[0] = *(const float4*)&As[kk][tm];
            *(float4*)&a[4] = *(const float4*)&As[kk][tm + 4];
            *(float4*)&w[0] = *(const float4*)&Ws[kk][tn];
            *(float4*)&w[4] = *(const float4*)&Ws[kk][tn + 4];
#pragma unroll
            for (int i = 0; i < 8; i++)
#pragma unroll
                for (int j = 0; j < 8; j++)
                    acc[i][j] = fmaf(a[i], w[j], acc[i][j]);
        }
        __syncthreads();
    }

    float bb[8];
    *(float4*)&bb[0] = *(const float4*)&bias[colBase + tn];
    *(float4*)&bb[4] = *(const float4*)&bias[colBase + tn + 4];

#pragma unroll
    for (int i = 0; i < 8; i++) {
        int r = rowBase + tm + i;
        int t = r & (T_ - 1);
        int b = r >> 11;                       // r / T_
        float* dst = &g_xg[((size_t)t * B_ + b) * G_ + colBase + tn];
        float4 v0 = make_float4(acc[i][0] + bb[0], acc[i][1] + bb[1],
                                acc[i][2] + bb[2], acc[i][3] + bb[3]);
        float4 v1 = make_float4(acc[i][4] + bb[4], acc[i][5] + bb[5],
                                acc[i][6] + bb[6], acc[i][7] + bb[7]);
        *(float4*)&dst[0] = v0;
        *(float4*)&dst[4] = v1;
    }
}

// ---------------------------------------------------------------------------
// Kernel B: persistent recurrence. CTA j owns h-columns [4j, 4j+4) -> 16 gate
// columns {g*512 + 4j + c : g in 0..3, c in 0..3}. Wh slice and c-state stay
// in SMEM across all 2048 steps; only h is exchanged via global double buffer
// + grid barrier.
// SMEM (floats): Whs[512*16]=8192 | hs[32*516]=16512 | gs[16*32]=512 | cs[128]
// ---------------------------------------------------------------------------
#define SMEM_FLOATS (8192 + 16512 + 512 + 128)

__global__ __launch_bounds__(256) void lstm_rec(const float* __restrict__ W,
                                                const float* __restrict__ h0,
                                                const float* __restrict__ c0,
                                                float* __restrict__ out) {
    extern __shared__ float sm[];
    float* Whs = sm;                 // [k*16 + gl]
    float* hs  = sm + 8192;          // [b*516 + k] (padded stride kills conflicts)
    float* gs  = hs + 16512;         // [gl*32 + b]
    float* cs  = gs + 512;           // [hcl*32 + b]

    const int tid = threadIdx.x;
    const int j   = blockIdx.x;      // 0..127
    const int jb  = j * 4;

    // Load Wh slice: Whs[k][gl], gl = gtype*4 + hcl
    for (int e = tid; e < 8192; e += 256) {
        int k  = e >> 4;
        int gl = e & 15;
        int gcol = (gl >> 2) * 512 + jb + (gl & 3);
        Whs[k * 16 + gl] = W[(size_t)(512 + k) * 2048 + gcol];
    }
    // Init c state
    if (tid < 128) {
        int b = tid >> 2, hcl = tid & 3;
        cs[hcl * 32 + b] = c0[b * 512 + jb + hcl];
    }
    __shared__ unsigned s_pb;
    if (tid == 0) s_pb = *(volatile unsigned*)&g_bar_phase;  // stable pre-run value
    __syncthreads();

    const int b     = tid >> 3;           // 0..31
    const int g2    = tid & 7;            // pair index
    const int gl0   = g2 * 2;             // even; gl0,gl0+1 share gate type
    const int gcol0 = (gl0 >> 2) * 512 + jb + (gl0 & 3);

    for (int t = 0; t < T_; t++) {
        // Broadcast current h into SMEM
        const float* hsrc = (t == 0) ? h0 : g_h[t & 1];
        for (int i4 = tid; i4 < 4096; i4 += 256) {
            int bb = i4 >> 7, k4 = (i4 & 127) * 4;
            *(float4*)&hs[bb * 516 + k4] = *(const float4*)&hsrc[bb * 512 + k4];
        }
        __syncthreads();

        // Two K=512 dot products per thread (gates gl0, gl0+1 for batch b)
        float2 xg2 = *(const float2*)&g_xg[((size_t)t * B_ + b) * G_ + gcol0];
        float acc0 = xg2.x, acc1 = xg2.y;
        const float*  hrow = &hs[b * 516];
        const float2* wp   = (const float2*)Whs;   // wp[k*8 + g2]
#pragma unroll 8
        for (int k = 0; k < 512; k++) {
            float  hv = hrow[k];
            float2 w  = wp[k * 8 + g2];
            acc0 = fmaf(hv, w.x, acc0);
            acc1 = fmaf(hv, w.y, acc1);
        }
        gs[gl0 * 32 + b]       = acc0;
        gs[(gl0 + 1) * 32 + b] = acc1;
        __syncthreads();

        // Gate combine: 128 threads, one (b, hcl) each
        if (tid < 128) {
            int bb = tid >> 2, hcl = tid & 3;
            float iv = gs[(0  + hcl) * 32 + bb];
            float fv = gs[(4  + hcl) * 32 + bb];
            float gv = gs[(8  + hcl) * 32 + bb];
            float ov = gs[(12 + hcl) * 32 + bb];
            iv = 1.f / (1.f + expf(-iv));
            fv = 1.f / (1.f + expf(-fv));
            gv = tanhf(gv);
            ov = 1.f / (1.f + expf(-ov));
            float c = fv * cs[hcl * 32 + bb] + iv * gv;
            cs[hcl * 32 + bb] = c;
            float h = ov * tanhf(c);
            g_h[(t + 1) & 1][bb * 512 + jb + hcl] = h;
            out[((size_t)bb * T_ + t) * H_ + jb + hcl] = h;      // outputs[b][t][hc]
            if (t == T_ - 1) {
                out[(size_t)BT_ * H_ + bb * 512 + jb + hcl]            = h;  // h_T
                out[(size_t)BT_ * H_ + B_ * H_ + bb * 512 + jb + hcl]  = c;  // c_T
            }
        }
        __syncthreads();

        // Grid barrier (skip after last step). Monotone phase is replay-safe:
        // every CTA reads the pre-run phase before its first arrive, and count
        // self-resets each barrier.
        if (t < T_ - 1) {
            if (tid == 0) {
                __threadfence();
                unsigned ticket = atomicAdd(&g_bar_count, 1);
                if (ticket == NCTA_REC - 1) {
                    g_bar_count = 0;
                    __threadfence();
                    atomicAdd(&g_bar_phase, 1);
                } else {
                    unsigned target = s_pb + (unsigned)t + 1u;
                    while ((int)(*(volatile unsigned*)&g_bar_phase - target) < 0) {
                        __nanosleep(64);
                    }
                    __threadfence();
                }
            }
            __syncthreads();
        }
    }
}

// ---------------------------------------------------------------------------
// Launcher
// ---------------------------------------------------------------------------
extern "C" void kernel_launch(void* const* d_in, const int* in_sizes, int n_in,
                              void* d_out, int out_size) {
    const float* x    = (const float*)d_in[0];   // (B, T, D)
    const float* W    = (const float*)d_in[1];   // (D+H, 4H)
    const float* bias = (const float*)d_in[2];   // (4H,)
    const float* h0   = (const float*)d_in[3];   // (B, H)
    const float* c0   = (const float*)d_in[4];   // (B, H)
    float* out = (float*)d_out;                  // outputs | h_T | c_T

    // Kernel A: xg = x @ Wx + b  (grid.x over N tiles keeps A rows hot in L2)
    dim3 grid(G_ / 128, BT_ / 128);
    xg_gemm<<<grid, 256>>>(x, W, bias);

    // Kernel B: persistent recurrence
    size_t smem = SMEM_FLOATS * sizeof(float);
    cudaFuncSetAttribute(lstm_rec, cudaFuncAttributeMaxDynamicSharedMemorySize,
                         (int)smem);
    lstm_rec<<<NCTA_REC, 256, smem>>>(W, h0, c0, out);
}